// round 10
// baseline (speedup 1.0000x reference)
#include <cuda_runtime.h>

#define NN 100000
#define EE 1250000
#define HH 64
#define TOT (EE + NN)

// ---------------- scratch (__device__ globals; no runtime allocation) ----------------
__device__ __align__(16) float d_dinv[NN];        // rsqrt of weighted degree
__device__ __align__(16) int   d_cnt[NN + 1];     // in-degree counts (incl. self loop)
__device__ __align__(16) int   d_part[NN + 1];    // per-block scan partials
__device__ __align__(16) int   d_bsums[128];      // block sums for scan
__device__ __align__(16) int   d_off[NN + 1];     // CSR row offsets
__device__ __align__(16) int   d_pos[NN];         // fill cursors
__device__ __align__(16) int   d_csr_src[TOT];
__device__ __align__(16) float d_csr_w[TOT];
__device__ __align__(16) float d_hA[NN * HH];
__device__ __align__(16) float d_hB[NN * HH];
__device__ __align__(16) float d_gg[NN * HH];

// ---------------- graph preprocessing (int atomics only; int32 indices!) ----------------
__global__ void k_init() {
    int i = blockIdx.x * blockDim.x + threadIdx.x;
    if (i < NN) d_cnt[i] = 1;          // self loop
    if (i == 0) d_cnt[NN] = 0;
}

__global__ void k_cnt(const int* __restrict__ ei) {
    int e = blockIdx.x * blockDim.x + threadIdx.x;
    if (e < EE) {
        int dd = ei[EE + e];           // row 1 = dst
        atomicAdd(&d_cnt[dd], 1);
    }
}

// exclusive scan of d_cnt[0..NN] -> d_off (3-stage)
__global__ void k_scan1() {
    __shared__ int sm[1024];
    int gid = blockIdx.x * 1024 + threadIdx.x;
    int v = (gid <= NN) ? d_cnt[gid] : 0;
    sm[threadIdx.x] = v;
    __syncthreads();
    for (int off = 1; off < 1024; off <<= 1) {
        int t = (threadIdx.x >= off) ? sm[threadIdx.x - off] : 0;
        __syncthreads();
        sm[threadIdx.x] += t;
        __syncthreads();
    }
    if (gid <= NN) d_part[gid] = sm[threadIdx.x] - v;   // exclusive within block
    if (threadIdx.x == 1023) d_bsums[blockIdx.x] = sm[1023];
}

__global__ void k_scan2(int nb) {
    if (threadIdx.x == 0 && blockIdx.x == 0) {
        int run = 0;
        for (int b = 0; b < nb; b++) { int v = d_bsums[b]; d_bsums[b] = run; run += v; }
    }
}

__global__ void k_scan3() {
    int gid = blockIdx.x * blockDim.x + threadIdx.x;
    if (gid <= NN) {
        int o = d_part[gid] + d_bsums[gid >> 10];
        d_off[gid] = o;
        if (gid < NN) d_pos[gid] = o;
    }
}

// fill CSR with RAW weights (ea for edges, 1.0 for self loops)
__global__ void k_fill(const int* __restrict__ ei, const float* __restrict__ ea) {
    int idx = blockIdx.x * blockDim.x + threadIdx.x;
    if (idx < EE) {
        int s  = ei[idx];              // row 0 = src
        int dd = ei[EE + idx];         // row 1 = dst
        int p = atomicAdd(&d_pos[dd], 1);
        d_csr_src[p] = s;
        d_csr_w[p]  = ea[idx];
    } else if (idx < TOT) {
        int i = idx - EE;
        int p = atomicAdd(&d_pos[i], 1);
        d_csr_src[p] = i;
        d_csr_w[p]  = 1.0f;
    }
}

// per-node weighted degree -> dinv (no atomics)
__global__ void k_dinv() {
    int i = blockIdx.x * blockDim.x + threadIdx.x;
    if (i >= NN) return;
    int beg = d_off[i], end = d_off[i + 1];
    float s = 0.f;
    for (int p = beg; p < end; p++) s += d_csr_w[p];
    d_dinv[i] = rsqrtf(s);   // deg >= 1 always (self loop)
}

// symmetric normalization in place: w <- dinv[src] * w * dinv[dst]
__global__ void k_norm() {
    int i = blockIdx.x * blockDim.x + threadIdx.x;
    if (i >= NN) return;
    int beg = d_off[i], end = d_off[i + 1];
    float di = d_dinv[i];
    for (int p = beg; p < end; p++)
        d_csr_w[p] = d_dinv[d_csr_src[p]] * d_csr_w[p] * di;
}

// ---------------- layer 1: scalar aggregate (x is N x 1), then rank-1 expand ----------------
__global__ void k_layer1(const float* __restrict__ x, const float* __restrict__ W1,
                         const float* __restrict__ b1) {
    int i = blockIdx.x * blockDim.x + threadIdx.x;
    if (i >= NN) return;
    int beg = d_off[i], end = d_off[i + 1];
    float s = 0.f;
    for (int p = beg; p < end; p++)
        s = fmaf(d_csr_w[p], x[d_csr_src[p]], s);
    const float4* W4 = (const float4*)W1;
    const float4* B4 = (const float4*)b1;
    float4* o = (float4*)(d_hA + i * HH);
#pragma unroll
    for (int j = 0; j < 16; j++) {
        float4 w = W4[j], b = B4[j], r;
        r.x = fmaxf(fmaf(s, w.x, b.x), 0.f);
        r.y = fmaxf(fmaf(s, w.y, b.y), 0.f);
        r.z = fmaxf(fmaf(s, w.z, b.z), 0.f);
        r.w = fmaxf(fmaf(s, w.w, b.w), 0.f);
        o[j] = r;
    }
}

// ---------------- GEMM: g = A @ W  (A selected by flag) ----------------
__global__ void __launch_bounds__(64) k_gemm(int asel, const float* __restrict__ W) {
    __shared__ float  As[64 * 65];
    __shared__ float4 Ws[64 * 16];
    const float* A = asel ? d_hB : d_hA;
    int tid  = threadIdx.x;
    int base = blockIdx.x * 64;

    const float4* W4 = (const float4*)W;
    for (int i = tid; i < 64 * 16; i += 64) Ws[i] = W4[i];
    for (int i = tid; i < 64 * 64; i += 64) {
        int r = i >> 6, c = i & 63;
        int node = base + r;
        As[r * 65 + c] = (node < NN) ? A[node * HH + c] : 0.f;
    }
    __syncthreads();

    float4 acc[16];
#pragma unroll
    for (int j = 0; j < 16; j++) acc[j] = make_float4(0.f, 0.f, 0.f, 0.f);

#pragma unroll 8
    for (int k = 0; k < 64; k++) {
        float a = As[tid * 65 + k];
#pragma unroll
        for (int j = 0; j < 16; j++) {
            float4 w = Ws[k * 16 + j];
            acc[j].x = fmaf(a, w.x, acc[j].x);
            acc[j].y = fmaf(a, w.y, acc[j].y);
            acc[j].z = fmaf(a, w.z, acc[j].z);
            acc[j].w = fmaf(a, w.w, acc[j].w);
        }
    }

    int node = base + tid;
    if (node < NN) {
        float4* o = (float4*)(d_gg + node * HH);
#pragma unroll
        for (int j = 0; j < 16; j++) o[j] = acc[j];
    }
}

// ---------------- aggregate: out = relu( sum_j w_ij * g[j] + b ), warp per node ----------------
__global__ void __launch_bounds__(256) k_agg(int osel, const float* __restrict__ bias) {
    float* out = osel ? d_hB : d_hA;
    const float* __restrict__ g = d_gg;
    int warp = (blockIdx.x * blockDim.x + threadIdx.x) >> 5;
    int lane = threadIdx.x & 31;
    if (warp >= NN) return;
    int beg = d_off[warp], end = d_off[warp + 1];
    float ax = 0.f, ay = 0.f;
    for (int base = beg; base < end; base += 32) {
        int n = min(32, end - base);
        int j = 0; float w = 0.f;
        if (lane < n) { j = d_csr_src[base + lane]; w = d_csr_w[base + lane]; }
        for (int t = 0; t < n; t++) {
            int   jj = __shfl_sync(0xffffffffu, j, t);
            float ww = __shfl_sync(0xffffffffu, w, t);
            float2 hv = *(const float2*)(g + jj * HH + 2 * lane);
            ax = fmaf(ww, hv.x, ax);
            ay = fmaf(ww, hv.y, ay);
        }
    }
    float2 b = *(const float2*)(bias + 2 * lane);
    ax = fmaxf(ax + b.x, 0.f);
    ay = fmaxf(ay + b.y, 0.f);
    *(float2*)(out + warp * HH + 2 * lane) = make_float2(ax, ay);
}

// ---------------- fused final MLP: out = relu(h5 @ fW1 + fb1) @ fW2 + fb2 ----------------
__global__ void __launch_bounds__(64) k_final(const float* __restrict__ fW1,
                                              const float* __restrict__ fb1,
                                              const float* __restrict__ fW2,
                                              const float* __restrict__ fb2,
                                              float* __restrict__ out) {
    __shared__ float  As[64 * 65];
    __shared__ float4 Ws[64 * 16];
    const float* A = d_hA;   // h5 lives in hA
    int tid  = threadIdx.x;
    int base = blockIdx.x * 64;

    const float4* W4 = (const float4*)fW1;
    for (int i = tid; i < 64 * 16; i += 64) Ws[i] = W4[i];
    for (int i = tid; i < 64 * 64; i += 64) {
        int r = i >> 6, c = i & 63;
        int node = base + r;
        As[r * 65 + c] = (node < NN) ? A[node * HH + c] : 0.f;
    }
    __syncthreads();

    float4 acc[16];
#pragma unroll
    for (int j = 0; j < 16; j++) acc[j] = make_float4(0.f, 0.f, 0.f, 0.f);

#pragma unroll 8
    for (int k = 0; k < 64; k++) {
        float a = As[tid * 65 + k];
#pragma unroll
        for (int j = 0; j < 16; j++) {
            float4 w = Ws[k * 16 + j];
            acc[j].x = fmaf(a, w.x, acc[j].x);
            acc[j].y = fmaf(a, w.y, acc[j].y);
            acc[j].z = fmaf(a, w.z, acc[j].z);
            acc[j].w = fmaf(a, w.w, acc[j].w);
        }
    }

    int node = base + tid;
    if (node < NN) {
        const float4* B4 = (const float4*)fb1;
        const float4* V4 = (const float4*)fW2;
        float r = fb2[0];
#pragma unroll
        for (int j = 0; j < 16; j++) {
            float4 b = B4[j], v = V4[j];
            float zx = fmaxf(acc[j].x + b.x, 0.f);
            float zy = fmaxf(acc[j].y + b.y, 0.f);
            float zz = fmaxf(acc[j].z + b.z, 0.f);
            float zw = fmaxf(acc[j].w + b.w, 0.f);
            r = fmaf(zx, v.x, r);
            r = fmaf(zy, v.y, r);
            r = fmaf(zz, v.z, r);
            r = fmaf(zw, v.w, r);
        }
        out[node] = r;
    }
}

// ---------------- launch ----------------
extern "C" void kernel_launch(void* const* d_in, const int* in_sizes, int n_in,
                              void* d_out, int out_size) {
    const float* x   = (const float*)d_in[0];
    const int*   ei  = (const int*)d_in[1];    // int32! (JAX default x64-disabled)
    const float* ea  = (const float*)d_in[2];
    const float* W1  = (const float*)d_in[3];
    const float* b1  = (const float*)d_in[4];
    const float* W2  = (const float*)d_in[5];
    const float* b2  = (const float*)d_in[6];
    const float* W3  = (const float*)d_in[7];
    const float* b3  = (const float*)d_in[8];
    const float* W4  = (const float*)d_in[9];
    const float* b4  = (const float*)d_in[10];
    const float* W5  = (const float*)d_in[11];
    const float* b5  = (const float*)d_in[12];
    const float* fW1 = (const float*)d_in[13];
    const float* fb1 = (const float*)d_in[14];
    const float* fW2 = (const float*)d_in[15];
    const float* fb2 = (const float*)d_in[16];
    float* out = (float*)d_out;

    const int TB = 256;
    int nblkN  = (NN + TB - 1) / TB;
    int nblkE  = (EE + TB - 1) / TB;
    int nblkT  = (TOT + TB - 1) / TB;
    int nblkN1 = (NN + 1 + TB - 1) / TB;
    int scanB  = (NN + 1 + 1023) / 1024;          // 98
    int gemmB  = (NN + 63) / 64;                  // 1563
    int aggB   = ((NN * 32) + TB - 1) / TB;       // 12500

    // graph prep (int atomics only; no float atomics)
    k_init  <<<nblkN, TB>>>();
    k_cnt   <<<nblkE, TB>>>(ei);
    k_scan1 <<<scanB, 1024>>>();
    k_scan2 <<<1, 32>>>(scanB);
    k_scan3 <<<nblkN1, TB>>>();
    k_fill  <<<nblkT, TB>>>(ei, ea);
    k_dinv  <<<nblkN, TB>>>();
    k_norm  <<<nblkN, TB>>>();

    // layer 1 (rank-1): h1 -> hA
    k_layer1<<<nblkN, TB>>>(x, W1, b1);

    // layer 2: g = hA @ W2 ; hB = relu(agg(g) + b2)
    k_gemm<<<gemmB, 64>>>(0, W2);
    k_agg <<<aggB, TB>>>(1, b2);
    // layer 3: hB -> hA
    k_gemm<<<gemmB, 64>>>(1, W3);
    k_agg <<<aggB, TB>>>(0, b3);
    // layer 4: hA -> hB
    k_gemm<<<gemmB, 64>>>(0, W4);
    k_agg <<<aggB, TB>>>(1, b4);
    // layer 5: hB -> hA
    k_gemm<<<gemmB, 64>>>(1, W5);
    k_agg <<<aggB, TB>>>(0, b5);

    // fused head
    k_final<<<gemmB, 64>>>(fW1, fb1, fW2, fb2, out);
}

// round 11
// speedup vs baseline: 1.1074x; 1.1074x over previous
#include <cuda_runtime.h>
#include <cuda_fp16.h>

#define NN 100000
#define EE 1250000
#define HH 64
#define TOT (EE + NN)

// ---------------- scratch (__device__ globals; no runtime allocation) ----------------
__device__ __align__(16) float  d_dinv[NN];        // rsqrt of weighted degree
__device__ __align__(16) int    d_cnt[NN + 1];     // in-degree counts (incl. self loop)
__device__ __align__(16) int    d_part[NN + 1];    // per-block scan partials
__device__ __align__(16) int    d_bsums[128];      // block sums for scan
__device__ __align__(16) int    d_off[NN + 1];     // CSR row offsets
__device__ __align__(16) int    d_pos[NN];         // fill cursors
__device__ __align__(16) int    d_csr_src[TOT];
__device__ __align__(16) float  d_csr_w[TOT];
__device__ __align__(16) float  d_hA[NN * HH];
__device__ __align__(16) float  d_hB[NN * HH];
__device__ __align__(16) __half d_g16[NN * HH];    // fp16-staged GEMM output (gathered)

// ---------------- graph preprocessing (int atomics only; int32 indices) ----------------
__global__ void k_init() {
    int i = blockIdx.x * blockDim.x + threadIdx.x;
    if (i < NN) d_cnt[i] = 1;          // self loop
    if (i == 0) d_cnt[NN] = 0;
}

__global__ void k_cnt(const int* __restrict__ ei) {
    int e = blockIdx.x * blockDim.x + threadIdx.x;
    if (e < EE) atomicAdd(&d_cnt[ei[EE + e]], 1);   // row 1 = dst
}

// exclusive scan of d_cnt[0..NN] -> d_off (3-stage)
__global__ void k_scan1() {
    __shared__ int sm[1024];
    int gid = blockIdx.x * 1024 + threadIdx.x;
    int v = (gid <= NN) ? d_cnt[gid] : 0;
    sm[threadIdx.x] = v;
    __syncthreads();
    for (int off = 1; off < 1024; off <<= 1) {
        int t = (threadIdx.x >= off) ? sm[threadIdx.x - off] : 0;
        __syncthreads();
        sm[threadIdx.x] += t;
        __syncthreads();
    }
    if (gid <= NN) d_part[gid] = sm[threadIdx.x] - v;   // exclusive within block
    if (threadIdx.x == 1023) d_bsums[blockIdx.x] = sm[1023];
}

__global__ void k_scan2(int nb) {   // parallel block-sum scan (nb <= 128)
    __shared__ int sm[128];
    int t = threadIdx.x;
    int v = (t < nb) ? d_bsums[t] : 0;
    sm[t] = v;
    __syncthreads();
    for (int off = 1; off < 128; off <<= 1) {
        int u = (t >= off) ? sm[t - off] : 0;
        __syncthreads();
        sm[t] += u;
        __syncthreads();
    }
    if (t < nb) d_bsums[t] = sm[t] - v;   // exclusive
}

__global__ void k_scan3() {
    int gid = blockIdx.x * blockDim.x + threadIdx.x;
    if (gid <= NN) {
        int o = d_part[gid] + d_bsums[gid >> 10];
        d_off[gid] = o;
        if (gid < NN) d_pos[gid] = o;
    }
}

// fill CSR with RAW weights (ea for edges, 1.0 for self loops)
__global__ void k_fill(const int* __restrict__ ei, const float* __restrict__ ea) {
    int idx = blockIdx.x * blockDim.x + threadIdx.x;
    if (idx < EE) {
        int s  = ei[idx];              // row 0 = src
        int dd = ei[EE + idx];         // row 1 = dst
        int p = atomicAdd(&d_pos[dd], 1);
        d_csr_src[p] = s;
        d_csr_w[p]  = ea[idx];
    } else if (idx < TOT) {
        int i = idx - EE;
        int p = atomicAdd(&d_pos[i], 1);
        d_csr_src[p] = i;
        d_csr_w[p]  = 1.0f;
    }
}

// per-node weighted degree -> dinv (no atomics)
__global__ void k_dinv() {
    int i = blockIdx.x * blockDim.x + threadIdx.x;
    if (i >= NN) return;
    int beg = d_off[i], end = d_off[i + 1];
    float s = 0.f;
    for (int p = beg; p < end; p++) s += d_csr_w[p];
    d_dinv[i] = rsqrtf(s);   // deg >= 1 always (self loop)
}

// fused: normalize row weights in place AND do layer-1 scalar aggregate + rank-1 expand
__global__ void k_norm_layer1(const float* __restrict__ x, const float* __restrict__ W1,
                              const float* __restrict__ b1) {
    int i = blockIdx.x * blockDim.x + threadIdx.x;
    if (i >= NN) return;
    int beg = d_off[i], end = d_off[i + 1];
    float di = d_dinv[i];
    float s = 0.f;
    for (int p = beg; p < end; p++) {
        int src = d_csr_src[p];
        float w = d_dinv[src] * d_csr_w[p] * di;   // symmetric normalization
        d_csr_w[p] = w;
        s = fmaf(w, x[src], s);                    // layer-1 scalar aggregate
    }
    const float4* W4 = (const float4*)W1;
    const float4* B4 = (const float4*)b1;
    float4* o = (float4*)(d_hA + i * HH);
#pragma unroll
    for (int j = 0; j < 16; j++) {
        float4 w = W4[j], b = B4[j], r;
        r.x = fmaxf(fmaf(s, w.x, b.x), 0.f);
        r.y = fmaxf(fmaf(s, w.y, b.y), 0.f);
        r.z = fmaxf(fmaf(s, w.z, b.z), 0.f);
        r.w = fmaxf(fmaf(s, w.w, b.w), 0.f);
        o[j] = r;
    }
}

// ---------------- GEMM: g16 = half(A @ W)  (A selected by flag) ----------------
__global__ void __launch_bounds__(64) k_gemm(int asel, const float* __restrict__ W) {
    __shared__ float  As[64 * 65];
    __shared__ float4 Ws[64 * 16];
    const float* A = asel ? d_hB : d_hA;
    int tid  = threadIdx.x;
    int base = blockIdx.x * 64;

    const float4* W4 = (const float4*)W;
    for (int i = tid; i < 64 * 16; i += 64) Ws[i] = W4[i];
    for (int i = tid; i < 64 * 64; i += 64) {
        int r = i >> 6, c = i & 63;
        int node = base + r;
        As[r * 65 + c] = (node < NN) ? A[node * HH + c] : 0.f;
    }
    __syncthreads();

    float4 acc[16];
#pragma unroll
    for (int j = 0; j < 16; j++) acc[j] = make_float4(0.f, 0.f, 0.f, 0.f);

#pragma unroll 8
    for (int k = 0; k < 64; k++) {
        float a = As[tid * 65 + k];
#pragma unroll
        for (int j = 0; j < 16; j++) {
            float4 w = Ws[k * 16 + j];
            acc[j].x = fmaf(a, w.x, acc[j].x);
            acc[j].y = fmaf(a, w.y, acc[j].y);
            acc[j].z = fmaf(a, w.z, acc[j].z);
            acc[j].w = fmaf(a, w.w, acc[j].w);
        }
    }

    int node = base + tid;
    if (node < NN) {
        __align__(16) __half2 hbuf[32];
#pragma unroll
        for (int j = 0; j < 16; j++) {
            hbuf[2 * j]     = __floats2half2_rn(acc[j].x, acc[j].y);
            hbuf[2 * j + 1] = __floats2half2_rn(acc[j].z, acc[j].w);
        }
        uint4* dst = (uint4*)(d_g16 + node * HH);
        const uint4* srcp = (const uint4*)hbuf;
#pragma unroll
        for (int i = 0; i < 8; i++) dst[i] = srcp[i];
    }
}

// ---------------- aggregate: out = relu( sum_j w_ij * g16[j] + b ), warp per node ----------------
__global__ void __launch_bounds__(256) k_agg(int osel, const float* __restrict__ bias) {
    float* out = osel ? d_hB : d_hA;
    const __half2* __restrict__ g = (const __half2*)d_g16;   // [NN][32]
    int warp = (blockIdx.x * blockDim.x + threadIdx.x) >> 5;
    int lane = threadIdx.x & 31;
    if (warp >= NN) return;
    int beg = d_off[warp], end = d_off[warp + 1];
    float ax = 0.f, ay = 0.f;
    for (int base = beg; base < end; base += 32) {
        int n = min(32, end - base);
        int j = 0; float w = 0.f;
        if (lane < n) { j = d_csr_src[base + lane]; w = d_csr_w[base + lane]; }
        for (int t = 0; t < n; t++) {
            int   jj = __shfl_sync(0xffffffffu, j, t);
            float ww = __shfl_sync(0xffffffffu, w, t);
            float2 hv = __half22float2(g[jj * 32 + lane]);
            ax = fmaf(ww, hv.x, ax);
            ay = fmaf(ww, hv.y, ay);
        }
    }
    float2 b = *(const float2*)(bias + 2 * lane);
    ax = fmaxf(ax + b.x, 0.f);
    ay = fmaxf(ay + b.y, 0.f);
    *(float2*)(out + warp * HH + 2 * lane) = make_float2(ax, ay);
}

// ---------------- fused final MLP: out = relu(h5 @ fW1 + fb1) @ fW2 + fb2 ----------------
__global__ void __launch_bounds__(64) k_final(const float* __restrict__ fW1,
                                              const float* __restrict__ fb1,
                                              const float* __restrict__ fW2,
                                              const float* __restrict__ fb2,
                                              float* __restrict__ out) {
    __shared__ float  As[64 * 65];
    __shared__ float4 Ws[64 * 16];
    const float* A = d_hA;   // h5 lives in hA
    int tid  = threadIdx.x;
    int base = blockIdx.x * 64;

    const float4* W4 = (const float4*)fW1;
    for (int i = tid; i < 64 * 16; i += 64) Ws[i] = W4[i];
    for (int i = tid; i < 64 * 64; i += 64) {
        int r = i >> 6, c = i & 63;
        int node = base + r;
        As[r * 65 + c] = (node < NN) ? A[node * HH + c] : 0.f;
    }
    __syncthreads();

    float4 acc[16];
#pragma unroll
    for (int j = 0; j < 16; j++) acc[j] = make_float4(0.f, 0.f, 0.f, 0.f);

#pragma unroll 8
    for (int k = 0; k < 64; k++) {
        float a = As[tid * 65 + k];
#pragma unroll
        for (int j = 0; j < 16; j++) {
            float4 w = Ws[k * 16 + j];
            acc[j].x = fmaf(a, w.x, acc[j].x);
            acc[j].y = fmaf(a, w.y, acc[j].y);
            acc[j].z = fmaf(a, w.z, acc[j].z);
            acc[j].w = fmaf(a, w.w, acc[j].w);
        }
    }

    int node = base + tid;
    if (node < NN) {
        const float4* B4 = (const float4*)fb1;
        const float4* V4 = (const float4*)fW2;
        float r = fb2[0];
#pragma unroll
        for (int j = 0; j < 16; j++) {
            float4 b = B4[j], v = V4[j];
            float zx = fmaxf(acc[j].x + b.x, 0.f);
            float zy = fmaxf(acc[j].y + b.y, 0.f);
            float zz = fmaxf(acc[j].z + b.z, 0.f);
            float zw = fmaxf(acc[j].w + b.w, 0.f);
            r = fmaf(zx, v.x, r);
            r = fmaf(zy, v.y, r);
            r = fmaf(zz, v.z, r);
            r = fmaf(zw, v.w, r);
        }
        out[node] = r;
    }
}

// ---------------- launch ----------------
extern "C" void kernel_launch(void* const* d_in, const int* in_sizes, int n_in,
                              void* d_out, int out_size) {
    const float* x   = (const float*)d_in[0];
    const int*   ei  = (const int*)d_in[1];    // int32 (JAX default x64-disabled)
    const float* ea  = (const float*)d_in[2];
    const float* W1  = (const float*)d_in[3];
    const float* b1  = (const float*)d_in[4];
    const float* W2  = (const float*)d_in[5];
    const float* b2  = (const float*)d_in[6];
    const float* W3  = (const float*)d_in[7];
    const float* b3  = (const float*)d_in[8];
    const float* W4  = (const float*)d_in[9];
    const float* b4  = (const float*)d_in[10];
    const float* W5  = (const float*)d_in[11];
    const float* b5  = (const float*)d_in[12];
    const float* fW1 = (const float*)d_in[13];
    const float* fb1 = (const float*)d_in[14];
    const float* fW2 = (const float*)d_in[15];
    const float* fb2 = (const float*)d_in[16];
    float* out = (float*)d_out;

    const int TB = 256;
    int nblkN  = (NN + TB - 1) / TB;
    int nblkE  = (EE + TB - 1) / TB;
    int nblkT  = (TOT + TB - 1) / TB;
    int nblkN1 = (NN + 1 + TB - 1) / TB;
    int scanB  = (NN + 1 + 1023) / 1024;          // 98
    int gemmB  = (NN + 63) / 64;                  // 1563
    int aggB   = ((NN * 32) + TB - 1) / TB;       // 12500

    // graph prep (int atomics only)
    k_init  <<<nblkN, TB>>>();
    k_cnt   <<<nblkE, TB>>>(ei);
    k_scan1 <<<scanB, 1024>>>();
    k_scan2 <<<1, 128>>>(scanB);
    k_scan3 <<<nblkN1, TB>>>();
    k_fill  <<<nblkT, TB>>>(ei, ea);
    k_dinv  <<<nblkN, TB>>>();

    // fused normalization + layer 1 (rank-1): h1 -> hA
    k_norm_layer1<<<nblkN, TB>>>(x, W1, b1);

    // layer 2: g = half(hA @ W2) ; hB = relu(agg(g) + b2)
    k_gemm<<<gemmB, 64>>>(0, W2);
    k_agg <<<aggB, TB>>>(1, b2);
    // layer 3: hB -> hA
    k_gemm<<<gemmB, 64>>>(1, W3);
    k_agg <<<aggB, TB>>>(0, b3);
    // layer 4: hA -> hB
    k_gemm<<<gemmB, 64>>>(0, W4);
    k_agg <<<aggB, TB>>>(1, b4);
    // layer 5: hB -> hA
    k_gemm<<<gemmB, 64>>>(1, W5);
    k_agg <<<aggB, TB>>>(0, b5);

    // fused head
    k_final<<<gemmB, 64>>>(fW1, fb1, fW2, fb2, out);
}

// round 12
// speedup vs baseline: 1.1853x; 1.0704x over previous
#include <cuda_runtime.h>
#include <cuda_fp16.h>

#define NN 100000
#define EE 1250000
#define HH 64
#define TOT (EE + NN)

#define FMA2(d, a, b) asm("fma.rn.f32x2 %0, %1, %2, %0;" : "+l"(d) : "l"(a), "l"(b))

// ---------------- scratch (__device__ globals; no runtime allocation) ----------------
__device__ __align__(16) float  d_dinv[NN];        // rsqrt of weighted degree
__device__ __align__(16) int    d_cnt[NN + 1];     // in-degree counts (incl. self loop)
__device__ __align__(16) int    d_part[NN + 1];    // per-block scan partials
__device__ __align__(16) int    d_bsums[128];      // block sums for scan
__device__ __align__(16) int    d_off[NN + 1];     // CSR row offsets
__device__ __align__(16) int    d_pos[NN];         // fill cursors
__device__ __align__(16) int2   d_csr_pair[TOT];   // {src, weight-as-int-bits}
__device__ __align__(16) float  d_hA[NN * HH];
__device__ __align__(16) float  d_hB[NN * HH];
__device__ __align__(16) __half d_g16[NN * HH];    // fp16-staged GEMM output (gathered)

// ---------------- graph preprocessing (int atomics only; int32 indices) ----------------
__global__ void k_init() {
    int i = blockIdx.x * blockDim.x + threadIdx.x;
    if (i < NN) d_cnt[i] = 1;          // self loop
    if (i == 0) d_cnt[NN] = 0;
}

__global__ void k_cnt(const int* __restrict__ ei) {
    int e = blockIdx.x * blockDim.x + threadIdx.x;
    if (e < EE) atomicAdd(&d_cnt[ei[EE + e]], 1);   // row 1 = dst
}

// exclusive scan of d_cnt[0..NN] -> d_off (3-stage)
__global__ void k_scan1() {
    __shared__ int sm[1024];
    int gid = blockIdx.x * 1024 + threadIdx.x;
    int v = (gid <= NN) ? d_cnt[gid] : 0;
    sm[threadIdx.x] = v;
    __syncthreads();
    for (int off = 1; off < 1024; off <<= 1) {
        int t = (threadIdx.x >= off) ? sm[threadIdx.x - off] : 0;
        __syncthreads();
        sm[threadIdx.x] += t;
        __syncthreads();
    }
    if (gid <= NN) d_part[gid] = sm[threadIdx.x] - v;   // exclusive within block
    if (threadIdx.x == 1023) d_bsums[blockIdx.x] = sm[1023];
}

__global__ void k_scan2(int nb) {   // parallel block-sum scan (nb <= 128)
    __shared__ int sm[128];
    int t = threadIdx.x;
    int v = (t < nb) ? d_bsums[t] : 0;
    sm[t] = v;
    __syncthreads();
    for (int off = 1; off < 128; off <<= 1) {
        int u = (t >= off) ? sm[t - off] : 0;
        __syncthreads();
        sm[t] += u;
        __syncthreads();
    }
    if (t < nb) d_bsums[t] = sm[t] - v;   // exclusive
}

__global__ void k_scan3() {
    int gid = blockIdx.x * blockDim.x + threadIdx.x;
    if (gid <= NN) {
        int o = d_part[gid] + d_bsums[gid >> 10];
        d_off[gid] = o;
        if (gid < NN) d_pos[gid] = o;
    }
}

// fill CSR with RAW weights (ea for edges, 1.0 for self loops)
__global__ void k_fill(const int* __restrict__ ei, const float* __restrict__ ea) {
    int idx = blockIdx.x * blockDim.x + threadIdx.x;
    if (idx < EE) {
        int s  = ei[idx];              // row 0 = src
        int dd = ei[EE + idx];         // row 1 = dst
        int p = atomicAdd(&d_pos[dd], 1);
        d_csr_pair[p] = make_int2(s, __float_as_int(ea[idx]));
    } else if (idx < TOT) {
        int i = idx - EE;
        int p = atomicAdd(&d_pos[i], 1);
        d_csr_pair[p] = make_int2(i, __float_as_int(1.0f));
    }
}

// per-node weighted degree -> dinv (no atomics)
__global__ void k_dinv() {
    int i = blockIdx.x * blockDim.x + threadIdx.x;
    if (i >= NN) return;
    int beg = d_off[i], end = d_off[i + 1];
    float s = 0.f;
    for (int p = beg; p < end; p++) s += __int_as_float(d_csr_pair[p].y);
    d_dinv[i] = rsqrtf(s);   // deg >= 1 always (self loop)
}

// fused: normalize row weights in place AND layer-1 scalar aggregate + rank-1 expand
__global__ void k_norm_layer1(const float* __restrict__ x, const float* __restrict__ W1,
                              const float* __restrict__ b1) {
    int i = blockIdx.x * blockDim.x + threadIdx.x;
    if (i >= NN) return;
    int beg = d_off[i], end = d_off[i + 1];
    float di = d_dinv[i];
    float s = 0.f;
    for (int p = beg; p < end; p++) {
        int2 pr = d_csr_pair[p];
        float w = d_dinv[pr.x] * __int_as_float(pr.y) * di;   // symmetric normalization
        d_csr_pair[p].y = __float_as_int(w);
        s = fmaf(w, x[pr.x], s);                              // layer-1 scalar aggregate
    }
    const float4* W4 = (const float4*)W1;
    const float4* B4 = (const float4*)b1;
    float4* o = (float4*)(d_hA + i * HH);
#pragma unroll
    for (int j = 0; j < 16; j++) {
        float4 w = W4[j], b = B4[j], r;
        r.x = fmaxf(fmaf(s, w.x, b.x), 0.f);
        r.y = fmaxf(fmaf(s, w.y, b.y), 0.f);
        r.z = fmaxf(fmaf(s, w.z, b.z), 0.f);
        r.w = fmaxf(fmaf(s, w.w, b.w), 0.f);
        o[j] = r;
    }
}

// ---------------- GEMM: g16 = half(A @ W) via packed f32x2 FMA ----------------
__global__ void __launch_bounds__(64) k_gemm(int asel, const float* __restrict__ W) {
    __shared__ float  As[64 * 65];
    __shared__ float4 Ws[64 * 16];
    const float* A = asel ? d_hB : d_hA;
    int tid  = threadIdx.x;
    int base = blockIdx.x * 64;

    const float4* W4 = (const float4*)W;
    for (int i = tid; i < 64 * 16; i += 64) Ws[i] = W4[i];
    for (int i = tid; i < 64 * 64; i += 64) {
        int r = i >> 6, c = i & 63;
        int node = base + r;
        As[r * 65 + c] = (node < NN) ? A[node * HH + c] : 0.f;
    }
    __syncthreads();

    unsigned long long acc[32];
#pragma unroll
    for (int j = 0; j < 32; j++) acc[j] = 0ull;   // bit pattern {0.f, 0.f}

#pragma unroll 4
    for (int k = 0; k < 64; k++) {
        float a = As[tid * 65 + k];
        unsigned long long aa;
        asm("mov.b64 %0, {%1, %1};" : "=l"(aa) : "f"(a));
        const ulonglong2* wrow = (const ulonglong2*)&Ws[k * 16];
#pragma unroll
        for (int j = 0; j < 16; j++) {
            ulonglong2 w2 = wrow[j];
            FMA2(acc[2 * j],     aa, w2.x);
            FMA2(acc[2 * j + 1], aa, w2.y);
        }
    }

    int node = base + tid;
    if (node < NN) {
        __align__(16) __half2 hbuf[32];
#pragma unroll
        for (int j = 0; j < 32; j++) {
            float lo, hi;
            asm("mov.b64 {%0, %1}, %2;" : "=f"(lo), "=f"(hi) : "l"(acc[j]));
            hbuf[j] = __floats2half2_rn(lo, hi);
        }
        uint4* dst = (uint4*)(d_g16 + node * HH);
        const uint4* srcp = (const uint4*)hbuf;
#pragma unroll
        for (int i = 0; i < 8; i++) dst[i] = srcp[i];
    }
}

// ---------------- aggregate: 2 nodes per warp, 16 lanes per node ----------------
// out[node] = relu( sum_j w_ij * g16[j] + b );  lane hl covers feature bytes [8hl, 8hl+8)
__global__ void __launch_bounds__(256) k_agg(int osel, const float* __restrict__ bias) {
    float* out = osel ? d_hB : d_hA;
    const unsigned long long* __restrict__ g = (const unsigned long long*)d_g16; // [NN][16]
    int gwarp = (blockIdx.x * blockDim.x + threadIdx.x) >> 5;
    int lane  = threadIdx.x & 31;
    int hl    = lane & 15;
    int node  = gwarp * 2 + (lane >> 4);          // NN even; grid sized exactly
    int beg = d_off[node], end = d_off[node + 1];
    int n = end - beg;
    int nmax = max(n, __shfl_xor_sync(0xffffffffu, n, 16));

    float a0 = 0.f, a1 = 0.f, a2 = 0.f, a3 = 0.f;
    for (int cb = 0; cb < nmax; cb += 16) {
        int jj = 0; float ww = 0.f;
        int my = cb + hl;
        if (my < n) {
            int2 p = d_csr_pair[beg + my];
            jj = p.x; ww = __int_as_float(p.y);
        }
        int lim    = min(16, nmax - cb);
        int my_lim = n - cb;                       // uniform per half-warp
        for (int t = 0; t < lim; t++) {
            int   j2 = __shfl_sync(0xffffffffu, jj, t, 16);
            float w2 = __shfl_sync(0xffffffffu, ww, t, 16);
            if (t < my_lim) {                      // predicated per half: no wasted loads
                unsigned long long hv = g[j2 * 16 + hl];
                unsigned int lo = (unsigned int)hv, hi = (unsigned int)(hv >> 32);
                float2 f0 = __half22float2(*reinterpret_cast<__half2*>(&lo));
                float2 f1 = __half22float2(*reinterpret_cast<__half2*>(&hi));
                a0 = fmaf(w2, f0.x, a0);
                a1 = fmaf(w2, f0.y, a1);
                a2 = fmaf(w2, f1.x, a2);
                a3 = fmaf(w2, f1.y, a3);
            }
        }
    }
    float4 b = *(const float4*)(bias + 4 * hl);
    float4 r;
    r.x = fmaxf(a0 + b.x, 0.f);
    r.y = fmaxf(a1 + b.y, 0.f);
    r.z = fmaxf(a2 + b.z, 0.f);
    r.w = fmaxf(a3 + b.w, 0.f);
    *(float4*)(out + node * HH + 4 * hl) = r;
}

// ---------------- fused final MLP: out = relu(h5 @ fW1 + fb1) @ fW2 + fb2 ----------------
__global__ void __launch_bounds__(64) k_final(const float* __restrict__ fW1,
                                              const float* __restrict__ fb1,
                                              const float* __restrict__ fW2,
                                              const float* __restrict__ fb2,
                                              float* __restrict__ out) {
    __shared__ float  As[64 * 65];
    __shared__ float4 Ws[64 * 16];
    const float* A = d_hA;   // h5 lives in hA
    int tid  = threadIdx.x;
    int base = blockIdx.x * 64;

    const float4* W4 = (const float4*)fW1;
    for (int i = tid; i < 64 * 16; i += 64) Ws[i] = W4[i];
    for (int i = tid; i < 64 * 64; i += 64) {
        int r = i >> 6, c = i & 63;
        int node = base + r;
        As[r * 65 + c] = (node < NN) ? A[node * HH + c] : 0.f;
    }
    __syncthreads();

    unsigned long long acc[32];
#pragma unroll
    for (int j = 0; j < 32; j++) acc[j] = 0ull;

#pragma unroll 4
    for (int k = 0; k < 64; k++) {
        float a = As[tid * 65 + k];
        unsigned long long aa;
        asm("mov.b64 %0, {%1, %1};" : "=l"(aa) : "f"(a));
        const ulonglong2* wrow = (const ulonglong2*)&Ws[k * 16];
#pragma unroll
        for (int j = 0; j < 16; j++) {
            ulonglong2 w2 = wrow[j];
            FMA2(acc[2 * j],     aa, w2.x);
            FMA2(acc[2 * j + 1], aa, w2.y);
        }
    }

    int node = base + tid;
    if (node < NN) {
        const float2* B2 = (const float2*)fb1;
        const float2* V2 = (const float2*)fW2;
        float r = fb2[0];
#pragma unroll
        for (int j = 0; j < 32; j++) {
            float lo, hi;
            asm("mov.b64 {%0, %1}, %2;" : "=f"(lo), "=f"(hi) : "l"(acc[j]));
            float2 b = B2[j], v = V2[j];
            float zx = fmaxf(lo + b.x, 0.f);
            float zy = fmaxf(hi + b.y, 0.f);
            r = fmaf(zx, v.x, r);
            r = fmaf(zy, v.y, r);
        }
        out[node] = r;
    }
}

// ---------------- launch ----------------
extern "C" void kernel_launch(void* const* d_in, const int* in_sizes, int n_in,
                              void* d_out, int out_size) {
    const float* x   = (const float*)d_in[0];
    const int*   ei  = (const int*)d_in[1];    // int32 (JAX default x64-disabled)
    const float* ea  = (const float*)d_in[2];
    const float* W1  = (const float*)d_in[3];
    const float* b1  = (const float*)d_in[4];
    const float* W2  = (const float*)d_in[5];
    const float* b2  = (const float*)d_in[6];
    const float* W3  = (const float*)d_in[7];
    const float* b3  = (const float*)d_in[8];
    const float* W4  = (const float*)d_in[9];
    const float* b4  = (const float*)d_in[10];
    const float* W5  = (const float*)d_in[11];
    const float* b5  = (const float*)d_in[12];
    const float* fW1 = (const float*)d_in[13];
    const float* fb1 = (const float*)d_in[14];
    const float* fW2 = (const float*)d_in[15];
    const float* fb2 = (const float*)d_in[16];
    float* out = (float*)d_out;

    const int TB = 256;
    int nblkN  = (NN + TB - 1) / TB;
    int nblkE  = (EE + TB - 1) / TB;
    int nblkT  = (TOT + TB - 1) / TB;
    int nblkN1 = (NN + 1 + TB - 1) / TB;
    int scanB  = (NN + 1 + 1023) / 1024;          // 98
    int gemmB  = (NN + 63) / 64;                  // 1563
    int aggB   = (NN / 2 * 32) / TB;              // 6250 (2 nodes/warp)

    // graph prep (int atomics only)
    k_init  <<<nblkN, TB>>>();
    k_cnt   <<<nblkE, TB>>>(ei);
    k_scan1 <<<scanB, 1024>>>();
    k_scan2 <<<1, 128>>>(scanB);
    k_scan3 <<<nblkN1, TB>>>();
    k_fill  <<<nblkT, TB>>>(ei, ea);
    k_dinv  <<<nblkN, TB>>>();

    // fused normalization + layer 1 (rank-1): h1 -> hA
    k_norm_layer1<<<nblkN, TB>>>(x, W1, b1);

    // layer 2: g = half(hA @ W2) ; hB = relu(agg(g) + b2)
    k_gemm<<<gemmB, 64>>>(0, W2);
    k_agg <<<aggB, TB>>>(1, b2);
    // layer 3: hB -> hA
    k_gemm<<<gemmB, 64>>>(1, W3);
    k_agg <<<aggB, TB>>>(0, b3);
    // layer 4: hA -> hB
    k_gemm<<<gemmB, 64>>>(0, W4);
    k_agg <<<aggB, TB>>>(1, b4);
    // layer 5: hB -> hA
    k_gemm<<<gemmB, 64>>>(1, W5);
    k_agg <<<aggB, TB>>>(0, b5);

    // fused head
    k_final<<<gemmB, 64>>>(fW1, fb1, fW2, fb2, out);
}